// round 15
// baseline (speedup 1.0000x reference)
#include <cuda_runtime.h>
#include <cstdint>

// FieldAwareFM: B=16384, F=10 fields, D=8.
// y[b] = b_lin + sum_f w[xoff[b,f]] + sum_{f<g} <emb[f, xoff[b,g]], emb[g, xoff[b,f]]>
//
// Best structure (12.544us) + single-wave pipelining:
//  - TWO samples per warp (16-lane halves), 12 pair-loads in flight per burst
//  - task t = l16 + 16k -> (pair p = t>>1, 16B half = t&1); adjacent lanes
//    read the two halves of one 32B row inside ONE LDG (sector sharing)
//  - pair (f,g) decode via packed 4-bit-per-lane immediate tables (no MUFU)
//  - FOUR samples per warp total: 2 parallel x 2 sequential iterations with
//    x-indices for both iterations prefetched up front (iter-2 prefix hidden)
//  - 512 blocks -> one fully-resident wave (4 blocks/SM), no wave transition

#define BATCH      16384
#define NUM_FIELDS 10
#define FACTOR_DIM 8
#define INPUT_DIM  188610
#define NPAIRS     45

__constant__ int c_off[NUM_FIELDS] = {
    0, 100000, 150000, 170000, 180000, 185000, 187000, 188000, 188500, 188600
};

// Nibble l16 of GTAB[k]/FTAB[k] = g/f of task t = l16 + 16k (pair p = t>>1),
// pairs enumerated g-DESC then f-ASC. k=5 lanes 10..15 invalid -> (f=0,g=1).
#define GTAB0 0x9999999999999999ULL
#define GTAB1 0x8888888888888899ULL
#define GTAB2 0x7777777777777788ULL
#define GTAB3 0x5555666666666666ULL
#define GTAB4 0x3344444444555555ULL
#define GTAB5 0x1111111122223333ULL

#define FTAB0 0x7766554433221100ULL
#define FTAB1 0x6655443322110088ULL
#define FTAB2 0x6655443322110077ULL
#define FTAB3 0x1100554433221100ULL
#define FTAB4 0x0033221100443322ULL
#define FTAB5 0x0000000011002211ULL

__global__ __launch_bounds__(256, 4) void ffm_kernel(
    const int*   __restrict__ x,       // (B, 10) int32
    const float* __restrict__ w,       // (INPUT_DIM,)
    const float* __restrict__ blin,    // scalar
    const float* __restrict__ emb,     // (10, INPUT_DIM, 8)
    float*       __restrict__ out)     // (B,)
{
    const unsigned FULL = 0xFFFFFFFFu;
    int wid  = (blockIdx.x * blockDim.x + threadIdx.x) >> 5;  // warp id
    int lane = threadIdx.x & 31;
    int h    = lane >> 4;              // sample half within warp
    int l16  = lane & 15;
    int bb   = wid * 4 + h;            // iteration 0 sample; iter 1 = bb+2

    const char* eb = (const char*)emb;
    const bool  fldlane = (l16 < NUM_FIELDS);

    // Prefetch raw x indices for BOTH iterations (warp covers 4 consecutive
    // samples = 160 contiguous bytes; coalesced).
    int xr0 = 0, xr1 = 0;
    if (fldlane) {
        xr0 = x[ bb      * NUM_FIELDS + l16];
        xr1 = x[(bb + 2) * NUM_FIELDS + l16];
    }

    const int   partB = (l16 & 1) << 4;  // 16B half select (t&1 == l16&1)
    const int   sh    = l16 * 4;         // nibble shift for this lane
    const float bl    = blin[0];

    const unsigned long long GT[6] = { GTAB0, GTAB1, GTAB2, GTAB3, GTAB4, GTAB5 };
    const unsigned long long FT[6] = { FTAB0, FTAB1, FTAB2, FTAB3, FTAB4, FTAB5 };

    #pragma unroll
    for (int it = 0; it < 2; it++) {
        int b  = bb + it * 2;
        int xr = it ? xr1 : xr0;

        // Half-lane f (<10) owns field f. V = byte offset of column x_off
        // within a field plane (= xoff * 32).
        int   V   = 0;
        float acc = 0.0f;
        if (fldlane) {
            int xo = xr + c_off[l16];
            V   = xo * 32;
            acc = w[xo];
        }

        float4 va[6], vb[6];
        bool   valid[6];

        #pragma unroll
        for (int k = 0; k < 6; k++) {
            // Immediate-table decode: g, f for task t = l16 + 16k.
            int g = (int)((GT[k] >> sh) & 15);
            int f = (int)((FT[k] >> sh) & 15);

            int vg = __shfl_sync(FULL, V, g, 16);   // byte key of x_g
            int vf = __shfl_sync(FULL, V, f, 16);   // byte key of x_f

            // A row = emb[f, x_g], B row = emb[g, x_f]
            const char* pA = eb + (unsigned)(f * (INPUT_DIM * 32)) + (unsigned)vg;
            const char* pB = eb + (unsigned)(g * (INPUT_DIM * 32)) + (unsigned)vf;

            valid[k] = (k < 5) | (l16 < 10);        // only k=5, l16>=10 invalid
            if (valid[k]) {
                va[k] = *(const float4*)(pA + partB);
                vb[k] = *(const float4*)(pB + partB);
            }
        }

        #pragma unroll
        for (int k = 0; k < 6; k++) {
            if (valid[k]) {
                acc += va[k].x * vb[k].x + va[k].y * vb[k].y
                     + va[k].z * vb[k].z + va[k].w * vb[k].w;
            }
        }

        // Reduction within each 16-lane half.
        #pragma unroll
        for (int o = 8; o > 0; o >>= 1)
            acc += __shfl_xor_sync(FULL, acc, o);

        if (l16 == 0)
            out[b] = acc + bl;
    }
}

extern "C" void kernel_launch(void* const* d_in, const int* in_sizes, int n_in,
                              void* d_out, int out_size) {
    const int*   x    = (const int*)  d_in[0];
    const float* w    = (const float*)d_in[1];
    const float* blin = (const float*)d_in[2];
    const float* emb  = (const float*)d_in[3];
    float* out = (float*)d_out;

    const int threads = 256;                      // 8 warps = 32 samples / block
    const int blocks  = (BATCH * 8) / threads;    // 512 -> one resident wave
    ffm_kernel<<<blocks, threads>>>(x, w, blin, emb, out);
}

// round 16
// speedup vs baseline: 1.0025x; 1.0025x over previous
#include <cuda_runtime.h>
#include <cstdint>

// FieldAwareFM: B=16384, F=10 fields, D=8.
// y[b] = b_lin + sum_f w[xoff[b,f]] + sum_{f<g} <emb[f, xoff[b,g]], emb[g, xoff[b,f]]>
//
// Best measured structure (12.544us): single kernel, TWO samples per warp
// (16-lane halves), 12 pair-loads in flight per warp, width-16 reduction,
// task t = l16 + 16k -> (pair p = t>>1, 16B half = t&1) with adjacent lanes
// sharing one 32B sector per LDG; pair (f,g) decode via packed 4-bit-per-lane
// immediate tables (no MUFU, no memory).
// Delta: branchless prologue — all 16 lanes issue the x/w loads with the lane
// clamped to field 9 (duplicate sectors, no extra wavefronts), removing the
// BSSY/BSYNC divergence that gated the 12 shuffles + 12 pair-loads.

#define BATCH      16384
#define NUM_FIELDS 10
#define FACTOR_DIM 8
#define INPUT_DIM  188610
#define NPAIRS     45

__constant__ int c_off[NUM_FIELDS] = {
    0, 100000, 150000, 170000, 180000, 185000, 187000, 188000, 188500, 188600
};

// Nibble l16 of GTAB[k]/FTAB[k] = g/f of task t = l16 + 16k (pair p = t>>1),
// pairs enumerated g-DESC then f-ASC. k=5 lanes 10..15 invalid -> (f=0,g=1).
#define GTAB0 0x9999999999999999ULL
#define GTAB1 0x8888888888888899ULL
#define GTAB2 0x7777777777777788ULL
#define GTAB3 0x5555666666666666ULL
#define GTAB4 0x3344444444555555ULL
#define GTAB5 0x1111111122223333ULL

#define FTAB0 0x7766554433221100ULL
#define FTAB1 0x6655443322110088ULL
#define FTAB2 0x6655443322110077ULL
#define FTAB3 0x1100554433221100ULL
#define FTAB4 0x0033221100443322ULL
#define FTAB5 0x0000000011002211ULL

__global__ __launch_bounds__(256, 4) void ffm_kernel(
    const int*   __restrict__ x,       // (B, 10) int32
    const float* __restrict__ w,       // (INPUT_DIM,)
    const float* __restrict__ blin,    // scalar
    const float* __restrict__ emb,     // (10, INPUT_DIM, 8)
    float*       __restrict__ out)     // (B,)
{
    const unsigned FULL = 0xFFFFFFFFu;
    int wid  = (blockIdx.x * blockDim.x + threadIdx.x) >> 5;  // warp id
    int lane = threadIdx.x & 31;
    int h    = lane >> 4;              // sample half within warp
    int l16  = lane & 15;
    int b    = wid * 2 + h;            // sample id; grid sized exactly

    const char* eb = (const char*)emb;

    // Branchless prologue: clamp lanes 10..15 to field 9 (their loads hit the
    // same sectors as lane 9; their V is never consumed since f,g <= 9).
    int   fld = l16 < 9 ? l16 : 9;     // min(l16, 9)
    int   xo  = x[b * NUM_FIELDS + fld] + c_off[fld];
    int   V   = xo * 32;               // byte offset within a field plane
    float wv  = w[xo];
    float acc = (l16 < NUM_FIELDS) ? wv : 0.0f;

    const int partB = (l16 & 1) << 4;  // 16B half select (t&1 == l16&1)
    const int sh    = l16 * 4;         // nibble shift for this lane

    const unsigned long long GT[6] = { GTAB0, GTAB1, GTAB2, GTAB3, GTAB4, GTAB5 };
    const unsigned long long FT[6] = { FTAB0, FTAB1, FTAB2, FTAB3, FTAB4, FTAB5 };

    float4 va[6], vb[6];
    bool   valid[6];

    #pragma unroll
    for (int k = 0; k < 6; k++) {
        // Immediate-table decode: g, f for task t = l16 + 16k.
        int g = (int)((GT[k] >> sh) & 15);
        int f = (int)((FT[k] >> sh) & 15);

        int vg = __shfl_sync(FULL, V, g, 16);   // byte key of x_g
        int vf = __shfl_sync(FULL, V, f, 16);   // byte key of x_f

        // A row = emb[f, x_g], B row = emb[g, x_f]
        const char* pA = eb + (unsigned)(f * (INPUT_DIM * 32)) + (unsigned)vg;
        const char* pB = eb + (unsigned)(g * (INPUT_DIM * 32)) + (unsigned)vf;

        valid[k] = (k < 5) | (l16 < 10);        // only k=5, l16>=10 invalid
        if (valid[k]) {
            va[k] = *(const float4*)(pA + partB);
            vb[k] = *(const float4*)(pB + partB);
        }
    }

    #pragma unroll
    for (int k = 0; k < 6; k++) {
        if (valid[k]) {
            acc += va[k].x * vb[k].x + va[k].y * vb[k].y
                 + va[k].z * vb[k].z + va[k].w * vb[k].w;
        }
    }

    // Reduction within each 16-lane half.
    #pragma unroll
    for (int o = 8; o > 0; o >>= 1)
        acc += __shfl_xor_sync(FULL, acc, o);

    if (l16 == 0)
        out[b] = acc + blin[0];
}

extern "C" void kernel_launch(void* const* d_in, const int* in_sizes, int n_in,
                              void* d_out, int out_size) {
    const int*   x    = (const int*)  d_in[0];
    const float* w    = (const float*)d_in[1];
    const float* blin = (const float*)d_in[2];
    const float* emb  = (const float*)d_in[3];
    float* out = (float*)d_out;

    const int threads = 256;                      // 8 warps = 16 samples / block
    const int blocks  = (BATCH * 16) / threads;   // 1024
    ffm_kernel<<<blocks, threads>>>(x, w, blin, emb, out);
}